// round 1
// baseline (speedup 1.0000x reference)
#include <cuda_runtime.h>

#define THREADS 256
#define ROWS_PER_BLOCK 8

// ---------------- shared memory layout (floats) ----------------
// w1s : [112][132]  (w1 transposed, row-padded to 132 for bank spread) 14784
// w2s : [128][32]   (w2 transposed)                                     4096
// perc: [112][128]  (first 32 rows double as new_state after GEMM2)    14336
// hs  : [128][128]  (hidden activations, relu'd)                       16384
// b1s[128] b2s[32] gs[32] bss[32] mus[128] rss[128] invs[128]            608
// total 50208 floats = 200832 bytes
#define SM_W1   0
#define SM_W2   (112*132)
#define SM_PERC (SM_W2 + 128*32)
#define SM_HS   (SM_PERC + 112*128)
#define SM_B1   (SM_HS + 128*128)
#define SM_B2   (SM_B1 + 128)
#define SM_G    (SM_B2 + 32)
#define SM_BETA (SM_G + 32)
#define SM_MU   (SM_BETA + 32)
#define SM_RS   (SM_MU + 128)
#define SM_INV  (SM_RS + 128)
#define SM_TOTAL (SM_INV + 128)

extern __shared__ float smem[];

__global__ void __launch_bounds__(THREADS)
cellnn_kernel(const float* __restrict__ x,
              const float* __restrict__ w1,
              const float* __restrict__ b1,
              const float* __restrict__ w2,
              const float* __restrict__ b2,
              const float* __restrict__ gamma,
              const float* __restrict__ beta,
              float* __restrict__ out)
{
    float* w1s  = smem + SM_W1;
    float* w2s  = smem + SM_W2;
    float* perc = smem + SM_PERC;   // first 32*128 floats alias new_state
    float* hs   = smem + SM_HS;
    float* b1s  = smem + SM_B1;
    float* b2s  = smem + SM_B2;
    float* gs   = smem + SM_G;
    float* bss  = smem + SM_BETA;
    float* mus  = smem + SM_MU;
    float* rss  = smem + SM_RS;
    float* invs = smem + SM_INV;

    const int tid = threadIdx.x;

    // ---- stage weights (once per block) ----
    for (int i = tid; i < 128 * 112; i += THREADS) {
        int o = i / 112;
        int k = i - o * 112;
        w1s[k * 132 + o] = w1[i];          // coalesced global read
    }
    for (int i = tid; i < 32 * 128; i += THREADS) {
        int o = i >> 7;
        int k = i & 127;
        w2s[k * 32 + o] = w2[i];
    }
    if (tid < 128) b1s[tid] = b1[tid];
    if (tid < 32) { b2s[tid] = b2[tid]; gs[tid] = gamma[tid]; bss[tid] = beta[tid]; }
    __syncthreads();

    const int row0 = blockIdx.x * ROWS_PER_BLOCK;        // global row index base
    const int bi   = row0 >> 7;                          // image index (128 rows/img)
    const float* xb = x   + (size_t)bi * 32 * 128 * 128;
    float*       ob = out + (size_t)bi * 32 * 128 * 128;

    for (int r = 0; r < ROWS_PER_BLOCK; ++r) {
        const int y = (row0 & 127) + r;

        // ---- build perc[112][128] for this row ----
        for (int i = tid; i < 32 * 128; i += THREADS) {
            int c = i >> 7, p = i & 127;
            perc[i] = xb[(c * 128 + y) * 128 + p];
        }
        for (int i = tid; i < 80 * 128; i += THREADS) {
            int kk = i >> 7, p = i & 127;
            int c  = kk >> 3, s = kk & 7;
            int idx = s + (s >= 4 ? 1 : 0);              // skip center tap
            int ki  = idx / 3;
            int dy  = ki - 1;
            int dx  = idx - ki * 3 - 1;
            int yy  = y + dy, xx = p + dx;
            float v = 0.0f;
            if ((unsigned)yy < 128u && (unsigned)xx < 128u)
                v = xb[(c * 128 + yy) * 128 + xx];
            perc[(32 + kk) * 128 + p] = v;
        }
        __syncthreads();

        // ---- GEMM1: h[128][128] = relu(W1 @ perc + b1) ----
        {
            const int p0 = (tid & 15) * 8;
            const int o0 = (tid >> 4) * 8;
            float acc[8][8];
            #pragma unroll
            for (int i = 0; i < 8; ++i)
                #pragma unroll
                for (int j = 0; j < 8; ++j) acc[i][j] = 0.0f;

            const float* pa = perc + p0;
            const float* pb = w1s + o0;
            #pragma unroll 2
            for (int k = 0; k < 112; ++k) {
                float4 a0 = *(const float4*)(pa + k * 128);
                float4 a1 = *(const float4*)(pa + k * 128 + 4);
                float4 c0 = *(const float4*)(pb + k * 132);
                float4 c1 = *(const float4*)(pb + k * 132 + 4);
                float av[8] = {a0.x, a0.y, a0.z, a0.w, a1.x, a1.y, a1.z, a1.w};
                float bv[8] = {c0.x, c0.y, c0.z, c0.w, c1.x, c1.y, c1.z, c1.w};
                #pragma unroll
                for (int i = 0; i < 8; ++i)
                    #pragma unroll
                    for (int j = 0; j < 8; ++j)
                        acc[i][j] = fmaf(av[i], bv[j], acc[i][j]);
            }
            #pragma unroll
            for (int j = 0; j < 8; ++j) {
                float bj = b1s[o0 + j];
                #pragma unroll
                for (int i = 0; i < 8; ++i) {
                    float h = acc[i][j] + bj;
                    hs[(o0 + j) * 128 + p0 + i] = fmaxf(h, 0.0f);
                }
            }
        }
        __syncthreads();

        // ---- GEMM2: dx[32][128] = W2 @ h + b2 ; new_state = x + dx (in place) ----
        {
            const int p0 = (tid & 15) * 8;
            const int c0 = (tid >> 4) * 2;
            float acc[8][2];
            #pragma unroll
            for (int i = 0; i < 8; ++i) { acc[i][0] = 0.0f; acc[i][1] = 0.0f; }

            const float* pa = hs + p0;
            const float* pb = w2s + c0;
            #pragma unroll 4
            for (int k = 0; k < 128; ++k) {
                float4 a0 = *(const float4*)(pa + k * 128);
                float4 a1 = *(const float4*)(pa + k * 128 + 4);
                float2 w  = *(const float2*)(pb + k * 32);
                float av[8] = {a0.x, a0.y, a0.z, a0.w, a1.x, a1.y, a1.z, a1.w};
                #pragma unroll
                for (int i = 0; i < 8; ++i) {
                    acc[i][0] = fmaf(av[i], w.x, acc[i][0]);
                    acc[i][1] = fmaf(av[i], w.y, acc[i][1]);
                }
            }
            #pragma unroll
            for (int j = 0; j < 2; ++j) {
                float bj = b2s[c0 + j];
                #pragma unroll
                for (int i = 0; i < 8; ++i) {
                    int off = (c0 + j) * 128 + p0 + i;
                    perc[off] = perc[off] + acc[i][j] + bj;   // new_state
                }
            }
        }
        __syncthreads();

        // ---- per-pixel stats: argmax mask, mean, var ----
        if (tid < 128) {
            const int p = tid;
            float best = perc[p];
            int arg = 0;
            #pragma unroll
            for (int c = 1; c < 10; ++c) {
                float v = perc[c * 128 + p];
                if (v > best) { best = v; arg = c; }
            }
            float factor = (arg != 0) ? 1.0f : 0.0f;
            float vals[32];
            float sum = 0.0f;
            #pragma unroll
            for (int c = 0; c < 32; ++c) {
                float v = perc[c * 128 + p];
                if (c >= 10) v *= factor;
                vals[c] = v;
                sum += v;
            }
            float mu = sum * (1.0f / 32.0f);
            float sq = 0.0f;
            #pragma unroll
            for (int c = 0; c < 32; ++c) {
                float d = vals[c] - mu;
                sq = fmaf(d, d, sq);
            }
            mus[p]  = mu;
            rss[p]  = rsqrtf(sq * (1.0f / 32.0f) + 1e-5f);
            invs[p] = factor;
        }
        __syncthreads();

        // ---- normalize + scale/shift + coalesced store ----
        for (int i = tid; i < 32 * 128; i += THREADS) {
            int c = i >> 7, p = i & 127;
            float v = perc[i];
            if (c >= 10) v *= invs[p];
            ob[(c * 128 + y) * 128 + p] = (v - mus[p]) * rss[p] * gs[c] + bss[c];
        }
        __syncthreads();   // protect perc/ns before next row rebuild
    }
}

extern "C" void kernel_launch(void* const* d_in, const int* in_sizes, int n_in,
                              void* d_out, int out_size)
{
    const float* x     = (const float*)d_in[0];
    const float* w1    = (const float*)d_in[1];
    const float* b1    = (const float*)d_in[2];
    const float* w2    = (const float*)d_in[3];
    const float* b2    = (const float*)d_in[4];
    const float* gamma = (const float*)d_in[5];
    const float* beta  = (const float*)d_in[6];
    float* out = (float*)d_out;

    const size_t smem_bytes = (size_t)SM_TOTAL * sizeof(float);   // 200832 B
    cudaFuncSetAttribute(cellnn_kernel,
                         cudaFuncAttributeMaxDynamicSharedMemorySize,
                         (int)smem_bytes);

    // 64 images * 128 rows / 8 rows per block = 1024 blocks
    cellnn_kernel<<<1024, THREADS, smem_bytes>>>(x, w1, b1, w2, b2, gamma, beta, out);
}

// round 3
// speedup vs baseline: 1.1091x; 1.1091x over previous
#include <cuda_runtime.h>
#include <cstdint>

#define THREADS 512
#define ROWS_PER_BLOCK 8

// ---------------- shared memory layout (floats) ----------------
#define SM_W1   0                       // [112][132] w1 transposed, padded
#define SM_W2   (112*132)               // [128][32]  w2 transposed
#define SM_PERC (SM_W2 + 128*32)        // [112][128] (first 32 rows reused as new_state)
#define SM_HS   (SM_PERC + 112*128)     // [128][128] hidden
#define SM_B1   (SM_HS + 128*128)
#define SM_B2   (SM_B1 + 128)
#define SM_G    (SM_B2 + 32)
#define SM_BETA (SM_G + 32)
#define SM_MU   (SM_BETA + 32)
#define SM_RS   (SM_MU + 128)
#define SM_INV  (SM_RS + 128)
#define SM_TOTAL (SM_INV + 128)         // 50208 floats = 200832 bytes

// packed f32x2 helpers (sm_100+ family; ptxas never emits these from C++)
__device__ __forceinline__ void ffma2(unsigned long long& d,
                                      unsigned long long a,
                                      unsigned long long b) {
    asm("fma.rn.f32x2 %0, %1, %2, %0;" : "+l"(d) : "l"(a), "l"(b));
}
__device__ __forceinline__ unsigned long long bcast2(float v) {
    unsigned long long r;
    asm("mov.b64 %0, {%1, %1};" : "=l"(r) : "f"(v));
    return r;
}
__device__ __forceinline__ void unpack2(unsigned long long p, float& lo, float& hi) {
    asm("mov.b64 {%0, %1}, %2;" : "=f"(lo), "=f"(hi) : "l"(p));
}

extern __shared__ float smem[];

__global__ void __launch_bounds__(THREADS)
cellnn_kernel(const float* __restrict__ x,
              const float* __restrict__ w1,
              const float* __restrict__ b1,
              const float* __restrict__ w2,
              const float* __restrict__ b2,
              const float* __restrict__ gamma,
              const float* __restrict__ beta,
              float* __restrict__ out)
{
    float* w1s  = smem + SM_W1;
    float* w2s  = smem + SM_W2;
    float* perc = smem + SM_PERC;
    float* hs   = smem + SM_HS;
    float* b1s  = smem + SM_B1;
    float* b2s  = smem + SM_B2;
    float* gs   = smem + SM_G;
    float* bss  = smem + SM_BETA;
    float* mus  = smem + SM_MU;
    float* rss  = smem + SM_RS;
    float* invs = smem + SM_INV;

    const int tid = threadIdx.x;

    // ---- stage weights (once per block) ----
    for (int i = tid; i < 128 * 112; i += THREADS) {
        int o = i / 112;
        int k = i - o * 112;
        w1s[k * 132 + o] = w1[i];
    }
    for (int i = tid; i < 32 * 128; i += THREADS) {
        int o = i >> 7;
        int k = i & 127;
        w2s[k * 32 + o] = w2[i];
    }
    if (tid < 128) b1s[tid] = b1[tid];
    if (tid < 32) { b2s[tid] = b2[tid]; gs[tid] = gamma[tid]; bss[tid] = beta[tid]; }
    __syncthreads();

    const int row0 = blockIdx.x * ROWS_PER_BLOCK;
    const int bi   = row0 >> 7;
    const float* xb = x   + (size_t)bi * 32 * 128 * 128;
    float*       ob = out + (size_t)bi * 32 * 128 * 128;

    for (int r = 0; r < ROWS_PER_BLOCK; ++r) {
        const int y = (row0 & 127) + r;

        // ---- build perc[112][128] ----
        for (int i = tid; i < 32 * 128; i += THREADS) {
            int c = i >> 7, p = i & 127;
            perc[i] = xb[(c * 128 + y) * 128 + p];
        }
        for (int i = tid; i < 80 * 128; i += THREADS) {
            int kk = i >> 7, p = i & 127;
            int c  = kk >> 3, s = kk & 7;
            int idx = s + (s >= 4 ? 1 : 0);
            int ki  = idx / 3;
            int dy  = ki - 1;
            int dx  = idx - ki * 3 - 1;
            int yy  = y + dy, xx = p + dx;
            float v = 0.0f;
            if ((unsigned)yy < 128u && (unsigned)xx < 128u)
                v = xb[(c * 128 + yy) * 128 + xx];
            perc[(32 + kk) * 128 + p] = v;
        }
        __syncthreads();

        // ---- GEMM1: h[128out][128px] = relu(W1 @ perc + b1), f32x2 px-pairs ----
        {
            const int p0 = (tid & 15) * 8;      // 8 pixels (4 f32x2 pairs)
            const int o0 = (tid >> 4) * 4;      // 4 outputs
            unsigned long long acc[4][4];       // [px_pair][out]
            #pragma unroll
            for (int i = 0; i < 4; ++i)
                #pragma unroll
                for (int j = 0; j < 4; ++j) acc[i][j] = 0ull;

            const float* pa = perc + p0;
            const float* pb = w1s + o0;
            #pragma unroll 2
            for (int k = 0; k < 112; ++k) {
                unsigned long long ap[4];
                #pragma unroll
                for (int i = 0; i < 4; ++i)
                    ap[i] = *(const unsigned long long*)(pa + k * 128 + 2 * i);
                float4 w = *(const float4*)(pb + k * 132);
                unsigned long long wb[4] = {bcast2(w.x), bcast2(w.y),
                                            bcast2(w.z), bcast2(w.w)};
                #pragma unroll
                for (int j = 0; j < 4; ++j)
                    #pragma unroll
                    for (int i = 0; i < 4; ++i)
                        ffma2(acc[i][j], ap[i], wb[j]);
            }
            #pragma unroll
            for (int j = 0; j < 4; ++j) {
                float bj = b1s[o0 + j];
                float hv[8];
                #pragma unroll
                for (int i = 0; i < 4; ++i) {
                    float lo, hi; unpack2(acc[i][j], lo, hi);
                    hv[2 * i]     = fmaxf(lo + bj, 0.0f);
                    hv[2 * i + 1] = fmaxf(hi + bj, 0.0f);
                }
                *(float4*)(hs + (o0 + j) * 128 + p0)     = make_float4(hv[0], hv[1], hv[2], hv[3]);
                *(float4*)(hs + (o0 + j) * 128 + p0 + 4) = make_float4(hv[4], hv[5], hv[6], hv[7]);
            }
        }
        __syncthreads();

        // ---- GEMM2: dx[32][128] = W2 @ h + b2 ; new_state in place ----
        {
            const int p0 = (tid & 15) * 8;
            const int c  = tid >> 4;            // one channel per thread group
            unsigned long long acc[4];
            #pragma unroll
            for (int i = 0; i < 4; ++i) acc[i] = 0ull;

            const float* pa = hs + p0;
            const float* pb = w2s + c;
            #pragma unroll 4
            for (int k = 0; k < 128; ++k) {
                unsigned long long wb = bcast2(pb[k * 32]);
                #pragma unroll
                for (int i = 0; i < 4; ++i) {
                    unsigned long long ap = *(const unsigned long long*)(pa + k * 128 + 2 * i);
                    ffma2(acc[i], ap, wb);
                }
            }
            float bj = b2s[c];
            #pragma unroll
            for (int i = 0; i < 4; ++i) {
                float lo, hi; unpack2(acc[i], lo, hi);
                int off = c * 128 + p0 + 2 * i;
                perc[off]     += lo + bj;
                perc[off + 1] += hi + bj;
            }
        }
        __syncthreads();

        // ---- per-pixel stats ----
        if (tid < 128) {
            const int p = tid;
            float best = perc[p];
            int arg = 0;
            #pragma unroll
            for (int c = 1; c < 10; ++c) {
                float v = perc[c * 128 + p];
                if (v > best) { best = v; arg = c; }
            }
            float factor = (arg != 0) ? 1.0f : 0.0f;
            float vals[32];
            float sum = 0.0f;
            #pragma unroll
            for (int c = 0; c < 32; ++c) {
                float v = perc[c * 128 + p];
                if (c >= 10) v *= factor;
                vals[c] = v;
                sum += v;
            }
            float mu = sum * (1.0f / 32.0f);
            float sq = 0.0f;
            #pragma unroll
            for (int c = 0; c < 32; ++c) {
                float d = vals[c] - mu;
                sq = fmaf(d, d, sq);
            }
            mus[p]  = mu;
            rss[p]  = rsqrtf(sq * (1.0f / 32.0f) + 1e-5f);
            invs[p] = factor;
        }
        __syncthreads();

        // ---- normalize + store ----
        for (int i = tid; i < 32 * 128; i += THREADS) {
            int c = i >> 7, p = i & 127;
            float v = perc[i];
            if (c >= 10) v *= invs[p];
            ob[(c * 128 + y) * 128 + p] = (v - mus[p]) * rss[p] * gs[c] + bss[c];
        }
        __syncthreads();
    }
}

extern "C" void kernel_launch(void* const* d_in, const int* in_sizes, int n_in,
                              void* d_out, int out_size)
{
    const float* x     = (const float*)d_in[0];
    const float* w1    = (const float*)d_in[1];
    const float* b1    = (const float*)d_in[2];
    const float* w2    = (const float*)d_in[3];
    const float* b2    = (const float*)d_in[4];
    const float* gamma = (const float*)d_in[5];
    const float* beta  = (const float*)d_in[6];
    float* out = (float*)d_out;

    const size_t smem_bytes = (size_t)SM_TOTAL * sizeof(float);
    cudaFuncSetAttribute(cellnn_kernel,
                         cudaFuncAttributeMaxDynamicSharedMemorySize,
                         (int)smem_bytes);

    cellnn_kernel<<<1024, THREADS, smem_bytes>>>(x, w1, b1, w2, b2, gamma, beta, out);
}

// round 4
// speedup vs baseline: 1.6473x; 1.4853x over previous
#include <cuda_runtime.h>
#include <cstdint>

#define THREADS 512
#define ROWS_PER_BLOCK 8

// ---------------- shared memory layout (floats) ----------------
#define SM_W1   0                       // [112][132] w1 transposed, padded
#define SM_W2   (112*132)               // [128][32]  w2 transposed
#define SM_PERC (SM_W2 + 128*32)        // [112][128] (rows 0..31 reused as new_state)
#define SM_HS   (SM_PERC + 112*128)     // [128][128] hidden (swizzled rows)
#define SM_B1   (SM_HS + 128*128)
#define SM_B2   (SM_B1 + 128)
#define SM_G    (SM_B2 + 32)
#define SM_BETA (SM_G + 32)
#define SM_MU   (SM_BETA + 32)
#define SM_RS   (SM_MU + 128)
#define SM_INV  (SM_RS + 128)
#define SM_TOTAL (SM_INV + 128)         // 50208 floats = 200832 bytes

// swizzle for hs (512-byte rows): decorrelate row index (bits 9+, taken at 11:13
// = row>>2 which varies with o_sub) into the 16B-granule bits [4:6]
#define SWZH(off) ((off) ^ (((off) >> 7) & 0x70))

// packed f32x2 helpers (sm_100+ family)
__device__ __forceinline__ void ffma2(unsigned long long& d,
                                      unsigned long long a,
                                      unsigned long long b) {
    asm("fma.rn.f32x2 %0, %1, %2, %0;" : "+l"(d) : "l"(a), "l"(b));
}
__device__ __forceinline__ unsigned long long bcast2(float v) {
    unsigned long long r;
    asm("mov.b64 %0, {%1, %1};" : "=l"(r) : "f"(v));
    return r;
}
__device__ __forceinline__ void unpack2(unsigned long long p, float& lo, float& hi) {
    asm("mov.b64 {%0, %1}, %2;" : "=f"(lo), "=f"(hi) : "l"(p));
}

extern __shared__ float smem[];

__global__ void __launch_bounds__(THREADS)
cellnn_kernel(const float* __restrict__ x,
              const float* __restrict__ w1,
              const float* __restrict__ b1,
              const float* __restrict__ w2,
              const float* __restrict__ b2,
              const float* __restrict__ gamma,
              const float* __restrict__ beta,
              float* __restrict__ out)
{
    float* w1s  = smem + SM_W1;
    float* w2s  = smem + SM_W2;
    float* perc = smem + SM_PERC;
    char*  hsb  = (char*)(smem + SM_HS);
    float* b1s  = smem + SM_B1;
    float* b2s  = smem + SM_B2;
    float* gs   = smem + SM_G;
    float* bss  = smem + SM_BETA;
    float* mus  = smem + SM_MU;
    float* rss  = smem + SM_RS;
    float* invs = smem + SM_INV;

    const int tid  = threadIdx.x;
    const int lane = tid & 31;
    const int warp = tid >> 5;

    // ---- stage weights (once per block) ----
    for (int i = tid; i < 128 * 112; i += THREADS) {
        int o = i / 112;
        int k = i - o * 112;
        w1s[k * 132 + o] = w1[i];
    }
    for (int i = tid; i < 32 * 128; i += THREADS) {
        int o = i >> 7;
        int k = i & 127;
        w2s[k * 32 + o] = w2[i];
    }
    if (tid < 128) b1s[tid] = b1[tid];
    if (tid < 32) { b2s[tid] = b2[tid]; gs[tid] = gamma[tid]; bss[tid] = beta[tid]; }
    __syncthreads();

    const int row0 = blockIdx.x * ROWS_PER_BLOCK;
    const int bi   = row0 >> 7;
    const float* xb = x   + (size_t)bi * 32 * 128 * 128;
    float*       ob = out + (size_t)bi * 32 * 128 * 128;

    // GEMM1 mapping: warp tile 32px x 32o
    const int px_sub = lane & 3;             // 4 px groups of 8 in warp
    const int o_sub  = lane >> 2;            // 8 o groups of 4 in warp
    const int px_blk = warp & 3;             // 4 px blocks of 32
    const int o_blk  = warp >> 2;            // 4 o blocks of 32
    const int g1_p0  = (px_blk * 4 + px_sub) * 8;
    const int g1_o0  = (o_blk * 8 + o_sub) * 4;
    // GEMM2 mapping: warp tile 32px x 8ch
    const int g2_p0  = g1_p0;
    const int g2_c   = (warp >> 2) * 8 + (lane >> 2);

    for (int r = 0; r < ROWS_PER_BLOCK; ++r) {
        const int y = (row0 & 127) + r;

        // ---- build perc[112][128] ----
        for (int i = tid; i < 32 * 128; i += THREADS) {
            int c = i >> 7, p = i & 127;
            perc[i] = xb[(c * 128 + y) * 128 + p];
        }
        for (int i = tid; i < 80 * 128; i += THREADS) {
            int kk = i >> 7, p = i & 127;
            int c  = kk >> 3, s = kk & 7;
            int idx = s + (s >= 4 ? 1 : 0);
            int ki  = idx / 3;
            int dy  = ki - 1;
            int dx  = idx - ki * 3 - 1;
            int yy  = y + dy, xx = p + dx;
            float v = 0.0f;
            if ((unsigned)yy < 128u && (unsigned)xx < 128u)
                v = xb[(c * 128 + yy) * 128 + xx];
            perc[(32 + kk) * 128 + p] = v;
        }
        __syncthreads();

        // ---- GEMM1: h[128o][128px] = relu(W1 @ perc + b1) ----
        {
            unsigned long long acc[4][4];       // [px_pair][o]
            #pragma unroll
            for (int i = 0; i < 4; ++i)
                #pragma unroll
                for (int j = 0; j < 4; ++j) acc[i][j] = 0ull;

            const float* pa = perc + g1_p0;
            const float* pb = w1s + g1_o0;
            #pragma unroll 2
            for (int k = 0; k < 112; ++k) {
                unsigned long long ap[4];
                #pragma unroll
                for (int i = 0; i < 4; ++i)
                    ap[i] = *(const unsigned long long*)(pa + k * 128 + 2 * i);
                float4 w = *(const float4*)(pb + k * 132);
                unsigned long long wb[4] = {bcast2(w.x), bcast2(w.y),
                                            bcast2(w.z), bcast2(w.w)};
                #pragma unroll
                for (int j = 0; j < 4; ++j)
                    #pragma unroll
                    for (int i = 0; i < 4; ++i)
                        ffma2(acc[i][j], ap[i], wb[j]);
            }
            #pragma unroll
            for (int j = 0; j < 4; ++j) {
                float bj = b1s[g1_o0 + j];
                float hv[8];
                #pragma unroll
                for (int i = 0; i < 4; ++i) {
                    float lo, hi; unpack2(acc[i][j], lo, hi);
                    hv[2 * i]     = fmaxf(lo + bj, 0.0f);
                    hv[2 * i + 1] = fmaxf(hi + bj, 0.0f);
                }
                uint32_t base = (uint32_t)((g1_o0 + j) * 512 + g1_p0 * 4);
                *(float4*)(hsb + SWZH(base))      = make_float4(hv[0], hv[1], hv[2], hv[3]);
                *(float4*)(hsb + SWZH(base + 16)) = make_float4(hv[4], hv[5], hv[6], hv[7]);
            }
        }
        __syncthreads();

        // ---- GEMM2: dx[32ch][128px] = W2 @ h + b2 ; new_state in place ----
        {
            unsigned long long acc[4];
            #pragma unroll
            for (int i = 0; i < 4; ++i) acc[i] = 0ull;

            const float* pb = w2s + g2_c;
            #pragma unroll 4
            for (int k = 0; k < 128; ++k) {
                unsigned long long wv = bcast2(pb[k * 32]);
                uint32_t rowb = (uint32_t)(k * 512 + g2_p0 * 4);
                #pragma unroll
                for (int i = 0; i < 4; ++i) {
                    unsigned long long ap =
                        *(const unsigned long long*)(hsb + SWZH(rowb + 8 * i));
                    ffma2(acc[i], ap, wv);
                }
            }
            float bj = b2s[g2_c];
            #pragma unroll
            for (int i = 0; i < 4; ++i) {
                float lo, hi; unpack2(acc[i], lo, hi);
                float2* dst = (float2*)(perc + g2_c * 128 + g2_p0 + 2 * i);
                float2 v = *dst;
                v.x += lo + bj;
                v.y += hi + bj;
                *dst = v;
            }
        }
        __syncthreads();

        // ---- per-pixel stats ----
        if (tid < 128) {
            const int p = tid;
            float best = perc[p];
            int arg = 0;
            #pragma unroll
            for (int c = 1; c < 10; ++c) {
                float v = perc[c * 128 + p];
                if (v > best) { best = v; arg = c; }
            }
            float factor = (arg != 0) ? 1.0f : 0.0f;
            float vals[32];
            float sum = 0.0f;
            #pragma unroll
            for (int c = 0; c < 32; ++c) {
                float v = perc[c * 128 + p];
                if (c >= 10) v *= factor;
                vals[c] = v;
                sum += v;
            }
            float mu = sum * (1.0f / 32.0f);
            float sq = 0.0f;
            #pragma unroll
            for (int c = 0; c < 32; ++c) {
                float d = vals[c] - mu;
                sq = fmaf(d, d, sq);
            }
            mus[p]  = mu;
            rss[p]  = rsqrtf(sq * (1.0f / 32.0f) + 1e-5f);
            invs[p] = factor;
        }
        __syncthreads();

        // ---- normalize + store ----
        for (int i = tid; i < 32 * 128; i += THREADS) {
            int c = i >> 7, p = i & 127;
            float v = perc[i];
            if (c >= 10) v *= invs[p];
            ob[(c * 128 + y) * 128 + p] = (v - mus[p]) * rss[p] * gs[c] + bss[c];
        }
        __syncthreads();
    }
}

extern "C" void kernel_launch(void* const* d_in, const int* in_sizes, int n_in,
                              void* d_out, int out_size)
{
    const float* x     = (const float*)d_in[0];
    const float* w1    = (const float*)d_in[1];
    const float* b1    = (const float*)d_in[2];
    const float* w2    = (const float*)d_in[3];
    const float* b2    = (const float*)d_in[4];
    const float* gamma = (const float*)d_in[5];
    const float* beta  = (const float*)d_in[6];
    float* out = (float*)d_out;

    const size_t smem_bytes = (size_t)SM_TOTAL * sizeof(float);
    cudaFuncSetAttribute(cellnn_kernel,
                         cudaFuncAttributeMaxDynamicSharedMemorySize,
                         (int)smem_bytes);

    cellnn_kernel<<<1024, THREADS, smem_bytes>>>(x, w1, b1, w2, b2, gamma, beta, out);
}